// round 17
// baseline (speedup 1.0000x reference)
#include <cuda_runtime.h>
#include <cstdint>

#define BB 512
#define TT 1024
#define NN 64
#define NJOBS (2 * BB)

// Bidirectional split of the CRF forward chain + LPT scheduling + fused
// combine (R14 schedule: scores inline in the forward job, combine on 2nd
// arrival, E precomputed in init). R17: duplicated-p exchange layout —
// smem holds (p_k, p_k) per row, E packed as (E[k][colA], E[k][colB]) so
// each fma.f32x2 accumulates (colA, colB) directly. This removes the
// horizontal add + repack from the step's serial epilogue (~15 cyc/step
// on the 512-step critical job).
//   Forward  job: q_t = diag(exp x_t) * E^T q_{t-1},  t = 1..nf  (+ scores)
//   Backward job: r_{k-1} = E * (exp(x_k) . r_k),      k = L-1..nf+1
//   log_norm = C_f + C_b + log(q_nf . r_nf);  out = sc - log_norm

__device__ float              g_qf[BB][NN];
__device__ float              g_rb[BB][NN];
__device__ float              g_cf[BB];
__device__ float              g_cb[BB];
__device__ float              g_sc[BB];
__device__ unsigned           g_ctr;
__device__ unsigned           g_done[BB];
__device__ unsigned short     g_order[NJOBS];
// E = exp(trans), packed for dup-p feed:
//   EF2[k][l] = (E[k][l],  E[k][l+32])    forward  (acc = (col l, col l+32))
//   EB2[k][l] = (E[l][k],  E[l+32][k])    backward (acc = (row l, row l+32))
__device__ unsigned long long g_EF2[NN][32];
__device__ unsigned long long g_EB2[NN][32];

// ---- init: counters, E tables, LPT rank over 1024 recurrence jobs ------
__global__ __launch_bounds__(NJOBS) void crf_init_kernel(
    const int*   __restrict__ lens,
    const float* __restrict__ trans)
{
    __shared__ unsigned hist[513];
    __shared__ unsigned ofs[513];
    __shared__ unsigned scan[NJOBS];
    const int tid = threadIdx.x;

    if (tid == 0) g_ctr = 0u;
    if (tid < BB) g_done[tid] = 0u;
    if (tid < 513) { hist[tid] = 0u; ofs[tid] = 0u; }

    // E tables: thread handles rows w and w+32 (w = tid>>5), lane l
    {
        const int w = tid >> 5;
        const int l = tid & 31;
        unsigned long long pk;
        float e0, e1;
#pragma unroll
        for (int kk = 0; kk < 2; ++kk) {
            const int k = w + 32 * kk;
            e0 = __expf(trans[k * NN + l]);
            e1 = __expf(trans[k * NN + l + 32]);
            asm("mov.b64 %0, {%1,%2};" : "=l"(pk) : "f"(e0), "f"(e1));
            g_EF2[k][l] = pk;
            e0 = __expf(trans[l * NN + k]);
            e1 = __expf(trans[(l + 32) * NN + k]);
            asm("mov.b64 %0, {%1,%2};" : "=l"(pk) : "f"(e0), "f"(e1));
            g_EB2[k][l] = pk;
        }
    }
    __syncthreads();

    const int b   = tid >> 1;
    const int dir = tid & 1;
    const int L   = lens[b];
    const int nf  = (L - 1) >> 1;
    const int len = dir ? (L - 1 - nf) : nf;   // 0..512
    atomicAdd(&hist[len], 1u);
    __syncthreads();

    scan[tid] = (tid <= 512) ? hist[512 - tid] : 0u;
    __syncthreads();
#pragma unroll
    for (int off = 1; off < NJOBS; off <<= 1) {
        unsigned v = (tid >= off) ? scan[tid - off] : 0u;
        __syncthreads();
        scan[tid] += v;
        __syncthreads();
    }

    const unsigned k     = (unsigned)(512 - len);
    const unsigned start = k ? scan[k - 1] : 0u;
    const unsigned pos   = start + atomicAdd(&ofs[len], 1u);
    g_order[pos] = (unsigned short)tid;
}

// load 16 dup rows (128B) as 8 x LDS.128 into u64[16]
#define LOAD_CHUNK16(dst, base)                                               \
    do {                                                                      \
        _Pragma("unroll")                                                     \
        for (int q8 = 0; q8 < 8; ++q8) {                                      \
            asm volatile("ld.shared.v2.u64 {%0,%1}, [%2];"                    \
                         : "=l"(dst[2 * q8]), "=l"(dst[2 * q8 + 1])           \
                         : "r"((base) + 16 * q8));                            \
        }                                                                     \
    } while (0)

// 16 FMAs over one chunk; 2 accumulator chains (reuse distance 6 cyc)
#define FMA_CHUNK16(g, vv)                                                    \
    do {                                                                      \
        _Pragma("unroll")                                                     \
        for (int k = 0; k < 16; k += 2) {                                     \
            asm("fma.rn.f32x2 %0, %1, %2, %0;"                                \
                : "+l"(c0) : "l"(E2[16 * (g) + k]),     "l"(vv[k]));          \
            asm("fma.rn.f32x2 %0, %1, %2, %0;"                                \
                : "+l"(c1) : "l"(E2[16 * (g) + k + 1]), "l"(vv[k + 1]));      \
        }                                                                     \
    } while (0)

// matvec: result c0 = packed (colA_sum, colB_sum)
#define MATVEC_NR(sbase)                                                      \
    unsigned long long v0[16], v1[16];                                        \
    LOAD_CHUNK16(v0, sbase);                                                  \
    LOAD_CHUNK16(v1, (sbase) + 128);                                          \
    unsigned long long c0 = 0ull, c1 = 0ull;                                  \
    FMA_CHUNK16(0, v0);                                                       \
    LOAD_CHUNK16(v0, (sbase) + 256);                                          \
    FMA_CHUNK16(1, v1);                                                       \
    LOAD_CHUNK16(v1, (sbase) + 384);                                          \
    FMA_CHUNK16(2, v0);                                                       \
    FMA_CHUNK16(3, v1);                                                       \
    asm("add.rn.f32x2 %0, %0, %1;" : "+l"(c0) : "l"(c1));

// renorm variant: exponent from dup word 0 (p_0) low half
#define MATVEC_RN(sbase)                                                      \
    unsigned long long v0[16], v1[16];                                        \
    LOAD_CHUNK16(v0, sbase);                                                  \
    LOAD_CHUNK16(v1, (sbase) + 128);                                          \
    unsigned q0bits;                                                          \
    asm("mov.b64 {%0,_}, %1;" : "=r"(q0bits) : "l"(v0[0]));                   \
    const int e = (int)((q0bits >> 23) & 0xff) - 127;                         \
    Ce += e;                                                                  \
    const float scale = __uint_as_float((unsigned)(127 - e) << 23);           \
    unsigned long long c0 = 0ull, c1 = 0ull;                                  \
    FMA_CHUNK16(0, v0);                                                       \
    LOAD_CHUNK16(v0, (sbase) + 256);                                          \
    FMA_CHUNK16(1, v1);                                                       \
    LOAD_CHUNK16(v1, (sbase) + 384);                                          \
    FMA_CHUNK16(2, v0);                                                       \
    FMA_CHUNK16(3, v1);                                                       \
    asm("add.rn.f32x2 %0, %0, %1;" : "+l"(c0) : "l"(c1));

// dup store: rows lane (A) and lane+32 (B)
#define STS_DUP(qa, qb)                                                       \
    do {                                                                      \
        asm volatile("st.shared.v2.f32 [%0], {%1,%1};"                        \
                     :: "r"(sstA), "f"(qa) : "memory");                       \
        asm volatile("st.shared.v2.f32 [%0], {%1,%1};"                        \
                     :: "r"(sstB), "f"(qb) : "memory");                       \
    } while (0)

#define PACK2(dst, lo, hi)                                                    \
    asm("mov.b64 %0, {%1,%2};" : "=l"(dst) : "f"(lo), "f"(hi))
#define UNPACK2(lo, hi, src)                                                  \
    asm("mov.b64 {%0,%1}, %2;" : "=f"(lo), "=f"(hi) : "l"(src))
#define MUL2(dst, a, b)                                                       \
    asm("mul.rn.f32x2 %0, %1, %2;" : "=l"(dst) : "l"(a), "l"(b))

// forward step: q = (E^T p) .* s2   (s2 carries sx and, on RN, the scale)
#define FSTEP_NR(xva, xvb)                                                    \
    do {                                                                      \
        unsigned long long s2;                                                \
        PACK2(s2, __expf(xva), __expf(xvb));                                  \
        MATVEC_NR(sw0);                                                       \
        unsigned long long q2;                                                \
        MUL2(q2, c0, s2);                                                     \
        UNPACK2(qa, qb, q2);                                                  \
        STS_DUP(qa, qb);                                                      \
    } while (0)

#define FSTEP_RN(xva, xvb)                                                    \
    do {                                                                      \
        const float sxa = __expf(xva);                                        \
        const float sxb = __expf(xvb);                                        \
        MATVEC_RN(sw0);                                                       \
        unsigned long long s2;                                                \
        PACK2(s2, sxa * scale, sxb * scale);                                  \
        unsigned long long q2;                                                \
        MUL2(q2, c0, s2);                                                     \
        UNPACK2(qa, qb, q2);                                                  \
        STS_DUP(qa, qb);                                                      \
    } while (0)

// backward step: u = sx .* r (store dup), then r = (E u) [* scale on RN]
#define BSTEP_NR(xva, xvb)                                                    \
    do {                                                                      \
        unsigned long long s2;                                                \
        PACK2(s2, __expf(xva), __expf(xvb));                                  \
        unsigned long long u2;                                                \
        MUL2(u2, rr, s2);                                                     \
        float ua, ub;                                                         \
        UNPACK2(ua, ub, u2);                                                  \
        STS_DUP(ua, ub);                                                      \
        MATVEC_NR(sw0);                                                       \
        rr = c0;                                                              \
    } while (0)

#define BSTEP_RN(xva, xvb)                                                    \
    do {                                                                      \
        unsigned long long s2;                                                \
        PACK2(s2, __expf(xva), __expf(xvb));                                  \
        unsigned long long u2;                                                \
        MUL2(u2, rr, s2);                                                     \
        float ua, ub;                                                         \
        UNPACK2(ua, ub, u2);                                                  \
        STS_DUP(ua, ub);                                                      \
        MATVEC_RN(sw0);                                                       \
        unsigned long long sc2;                                               \
        PACK2(sc2, scale, scale);                                             \
        MUL2(rr, c0, sc2);                                                    \
    } while (0)

__device__ __forceinline__ void crf_combine(int b, int lane,
                                            float* __restrict__ out)
{
    const float d0 = __ldcg(&g_qf[b][lane])      * __ldcg(&g_rb[b][lane]);
    const float d1 = __ldcg(&g_qf[b][lane + 32]) * __ldcg(&g_rb[b][lane + 32]);
    float d = d0 + d1;
#pragma unroll
    for (int o = 16; o; o >>= 1) d += __shfl_xor_sync(0xffffffffu, d, o);
    if (lane == 0) {
        const float log_norm = __ldcg(&g_cf[b]) + __ldcg(&g_cb[b]) + __logf(d);
        out[b] = __ldcg(&g_sc[b]) - log_norm;
    }
}

__global__ __launch_bounds__(128, 1) void crf_half_kernel(
    const float* __restrict__ inputs,   // [B, T, N]
    const float* __restrict__ trans,    // [N, N]
    const int*   __restrict__ tags,     // [B, T]
    const int*   __restrict__ lens,     // [B]
    float*       __restrict__ out)      // [B]
{
    const int lane = threadIdx.x & 31;
    const int wid  = threadIdx.x >> 5;

    __shared__ __align__(16) float2 pbuf[4][NN];   // dup rows, 512B/warp

    for (;;) {
        unsigned j;
        if (lane == 0) j = atomicAdd(&g_ctr, 1u);
        j = __shfl_sync(0xffffffffu, j, 0);
        if (j >= NJOBS) return;
        j = g_order[j];                      // LPT order

        const int b   = (int)(j >> 1);
        const int dir = (int)(j & 1);
        const int L   = lens[b];
        const int nf  = (L - 1) >> 1;
        const size_t tbase = (size_t)b * TT;
        const float* xp = inputs + tbase * NN;

        const unsigned sw0 =
            (unsigned)__cvta_generic_to_shared(&pbuf[wid][0]);
        const unsigned sstA = sw0 + (unsigned)(lane * 8);
        const unsigned sstB = sstA + 256;

        if (dir == 0) {
            // ---------------- FORWARD half + scores ----------------------
            float sc = 0.f;
            for (int t = lane; t < L; t += 32) {
                int tg = tags[tbase + t];
                sc += inputs[(tbase + t) * NN + tg];
                if (t >= 1) {
                    int tp = tags[tbase + t - 1];
                    sc += trans[tp * NN + tg];
                }
            }
#pragma unroll
            for (int o = 16; o; o >>= 1)
                sc += __shfl_xor_sync(0xffffffffu, sc, o);

            unsigned long long E2[NN];
#pragma unroll
            for (int k = 0; k < NN; ++k) E2[k] = g_EF2[k][lane];

            float x0a = xp[lane];
            float x0b = xp[lane + 32];
            float M0  = __shfl_sync(0xffffffffu, x0a, 0);
            float qa  = __expf(x0a - M0);
            float qb  = __expf(x0b - M0);
            STS_DUP(qa, qb);

            int Ce = 0;

            // preload x for t = 1..4 (rows <= 4 < TT, in-bounds)
            const float* xq = xp + NN;
            float xa0 = xq[lane],          xb0 = xq[lane + 32];
            float xa1 = xq[NN + lane],     xb1 = xq[NN + lane + 32];
            float xa2 = xq[2 * NN + lane], xb2 = xq[2 * NN + lane + 32];
            float xa3 = xq[3 * NN + lane], xb3 = xq[3 * NN + lane + 32];
            const float* xf = xp + 5 * NN;   // block-ahead pointer

            int t = 1;
            for (; t + 3 <= nf; t += 4) {
                const float ya0 = xf[lane],          yb0 = xf[lane + 32];
                const float ya1 = xf[NN + lane],     yb1 = xf[NN + lane + 32];
                const float ya2 = xf[2 * NN + lane], yb2 = xf[2 * NN + lane + 32];
                const float ya3 = xf[3 * NN + lane], yb3 = xf[3 * NN + lane + 32];

                FSTEP_NR(xa0, xb0);
                FSTEP_NR(xa1, xb1);
                FSTEP_NR(xa2, xb2);
                FSTEP_RN(xa3, xb3);

                xa0 = ya0; xb0 = yb0; xa1 = ya1; xb1 = yb1;
                xa2 = ya2; xb2 = yb2; xa3 = ya3; xb3 = yb3;
                xf += 4 * NN;
            }
            if (t     <= nf) { FSTEP_RN(xa0, xb0); }
            if (t + 1 <= nf) { FSTEP_RN(xa1, xb1); }
            if (t + 2 <= nf) { FSTEP_RN(xa2, xb2); }

            g_qf[b][lane]      = qa;
            g_qf[b][lane + 32] = qb;
            if (lane == 0) {
                g_cf[b] = M0 + (float)Ce * 0.6931471805599453f;
                g_sc[b] = sc;
            }
        } else {
            // ---------------- BACKWARD half ------------------------------
            unsigned long long E2[NN];
#pragma unroll
            for (int k = 0; k < NN; ++k) E2[k] = g_EB2[k][lane];

            const int nb = (L - 1) - nf;
            unsigned long long rr;
            PACK2(rr, 1.f, 1.f);
            int Ce = 0;

            // preload x for s = 0..3 (rows L-1-u, clamped >= 0)
            const int r0 = (L - 1) > 0 ? (L - 1) : 0;
            const int r1 = (L - 2) > 0 ? (L - 2) : 0;
            const int r2 = (L - 3) > 0 ? (L - 3) : 0;
            const int r3 = (L - 4) > 0 ? (L - 4) : 0;
            float xa0 = xp[r0 * NN + lane], xb0 = xp[r0 * NN + lane + 32];
            float xa1 = xp[r1 * NN + lane], xb1 = xp[r1 * NN + lane + 32];
            float xa2 = xp[r2 * NN + lane], xb2 = xp[r2 * NN + lane + 32];
            float xa3 = xp[r3 * NN + lane], xb3 = xp[r3 * NN + lane + 32];

            int kk = L - 5;   // row of next block's first prefetch
            int s = 0;
            for (; s + 3 < nb; s += 4) {
                const int c0r = kk     > 0 ? kk     : 0;
                const int c1r = kk - 1 > 0 ? kk - 1 : 0;
                const int c2r = kk - 2 > 0 ? kk - 2 : 0;
                const int c3r = kk - 3 > 0 ? kk - 3 : 0;
                const float ya0 = xp[c0r * NN + lane], yb0 = xp[c0r * NN + lane + 32];
                const float ya1 = xp[c1r * NN + lane], yb1 = xp[c1r * NN + lane + 32];
                const float ya2 = xp[c2r * NN + lane], yb2 = xp[c2r * NN + lane + 32];
                const float ya3 = xp[c3r * NN + lane], yb3 = xp[c3r * NN + lane + 32];

                BSTEP_NR(xa0, xb0);
                BSTEP_NR(xa1, xb1);
                BSTEP_NR(xa2, xb2);
                BSTEP_RN(xa3, xb3);

                xa0 = ya0; xb0 = yb0; xa1 = ya1; xb1 = yb1;
                xa2 = ya2; xb2 = yb2; xa3 = ya3; xb3 = yb3;
                kk -= 4;
            }
            if (s     < nb) { BSTEP_RN(xa0, xb0); }
            if (s + 1 < nb) { BSTEP_RN(xa1, xb1); }
            if (s + 2 < nb) { BSTEP_RN(xa2, xb2); }

            float ra, rb;
            UNPACK2(ra, rb, rr);
            g_rb[b][lane]      = ra;
            g_rb[b][lane + 32] = rb;
            if (lane == 0)
                g_cb[b] = (float)Ce * 0.6931471805599453f;
        }

        // ---- completion: second finisher combines ----
        __threadfence();
        unsigned old = 0;
        if (lane == 0) old = atomicAdd(&g_done[b], 1u);
        old = __shfl_sync(0xffffffffu, old, 0);
        if (old == 1u) {
            __threadfence();
            crf_combine(b, lane, out);
        }
    }
}

extern "C" void kernel_launch(void* const* d_in, const int* in_sizes, int n_in,
                              void* d_out, int out_size)
{
    const float* inputs = (const float*)d_in[0];
    const float* trans  = (const float*)d_in[1];
    const int*   tags   = (const int*)d_in[2];
    const int*   lens   = (const int*)d_in[3];
    float*       out    = (float*)d_out;

    crf_init_kernel<<<1, NJOBS>>>(lens, trans);
    crf_half_kernel<<<148, 128>>>(inputs, trans, tags, lens, out);
}